// round 15
// baseline (speedup 1.0000x reference)
#include <cuda_runtime.h>
#include <cuda_bf16.h>
#include <cuda_fp16.h>
#include <cstdint>

#define NN   3072
#define INF  512
#define NH   8
#define HD   64
#define OF   512   // NH*HD
#define MW   96    // mask words per row
#define KT4  128   // attn j quad-tile (four 32-j sub-tiles per sync)
#define MT   192   // attn i tile per CTA (6 i-ranges x 32 i)
#define NT4  (NN / KT4)
#define FSB  (((NN + OF) * INF) / 2048)   // fsplit blocks in prep_kernel

// ---------------- scratch ----------------
__device__ float         g_h[NN * OF];
__device__ float         g_P[NH * NN];
__device__ float         g_p[NH * NN];
__device__ float         g_Q[NH * NN];
__device__ float         g_q[NH * NN];
__device__ unsigned      g_QmU[NH];
__device__ unsigned      g_qmU[NH];
__device__ unsigned      g_mask[NN * MW];
__device__ __half        g_hTh[NH * HD * NN];      // [h][d][n], fp16 h (transposed)
__device__ __nv_bfloat16 g_X1[NN * INF];
__device__ __nv_bfloat16 g_X2[NN * INF];
__device__ __nv_bfloat16 g_W1[OF * INF];
__device__ __nv_bfloat16 g_W2[OF * INF];

__device__ __forceinline__ uint32_t smem_u32(const void* p) {
    uint32_t a;
    asm("{ .reg .u64 t; cvta.to.shared.u64 t, %1; cvt.u32.u64 %0, t; }" : "=r"(a) : "l"(p));
    return a;
}

__device__ __forceinline__ void mma_bf16(float* c, const uint32_t* a, uint32_t b0, uint32_t b1) {
    asm volatile(
        "mma.sync.aligned.m16n8k16.row.col.f32.bf16.bf16.f32 "
        "{%0,%1,%2,%3}, {%4,%5,%6,%7}, {%8,%9}, {%0,%1,%2,%3};"
        : "+f"(c[0]), "+f"(c[1]), "+f"(c[2]), "+f"(c[3])
        : "r"(a[0]), "r"(a[1]), "r"(a[2]), "r"(a[3]), "r"(b0), "r"(b1));
}

__device__ __forceinline__ void mma_f16(float* c, const uint32_t* a, uint32_t b0, uint32_t b1) {
    asm volatile(
        "mma.sync.aligned.m16n8k16.row.col.f32.f16.f16.f32 "
        "{%0,%1,%2,%3}, {%4,%5,%6,%7}, {%8,%9}, {%0,%1,%2,%3};"
        : "+f"(c[0]), "+f"(c[1]), "+f"(c[2]), "+f"(c[3])
        : "r"(a[0]), "r"(a[1]), "r"(a[2]), "r"(a[3]), "r"(b0), "r"(b1));
}

__device__ __forceinline__ void ldmx4(uint32_t* r, uint32_t addr) {
    asm volatile("ldmatrix.sync.aligned.m8n8.x4.shared.b16 {%0,%1,%2,%3}, [%4];"
                 : "=r"(r[0]), "=r"(r[1]), "=r"(r[2]), "=r"(r[3]) : "r"(addr));
}

__device__ __forceinline__ void split2(float w0, float w1, uint32_t& hi, uint32_t& lo) {
    uint32_t h;
    asm("cvt.rn.bf16x2.f32 %0, %1, %2;" : "=r"(h) : "f"(w1), "f"(w0));
    float r0 = w0 - __uint_as_float(h << 16);
    float r1 = w1 - __uint_as_float(h & 0xffff0000u);
    uint32_t l;
    asm("cvt.rn.bf16x2.f32 %0, %1, %2;" : "=r"(l) : "f"(r1), "f"(r0));
    hi = h; lo = l;
}

__device__ __forceinline__ uint32_t packh2(float b, float a) {
    uint32_t r;
    asm("cvt.rn.f16x2.f32 %0, %1, %2;" : "=r"(r) : "f"(b), "f"(a));
    return r;
}

// ---------------- Kernel 0: fused fsplit (X,W -> bf16 hi/lo) + adjacency mask ----------------
__global__ __launch_bounds__(256) void prep_kernel(const float* __restrict__ x,
                                                   const float* __restrict__ Wm,
                                                   const int* __restrict__ adj) {
    if (blockIdx.x < FSB) {
        const int gidx = blockIdx.x * blockDim.x + threadIdx.x;
        if (blockIdx.x == 0 && threadIdx.x < 2 * NH) {
            if (threadIdx.x < NH) g_QmU[threadIdx.x] = 0u;
            else                  g_qmU[threadIdx.x - NH] = 0u;
        }
        const int idx = gidx * 8;
        const float* src;
        __nv_bfloat16 *dhi, *dlo;
        int off;
        if (idx < NN * INF) {
            src = x; dhi = g_X1; dlo = g_X2; off = idx;
        } else {
            src = Wm; dhi = g_W1; dlo = g_W2; off = idx - NN * INF;
        }
        float4 v0 = *(const float4*)(src + off);
        float4 v1 = *(const float4*)(src + off + 4);
        uint32_t h0, h1, h2, h3, l0, l1, l2, l3;
        split2(v0.x, v0.y, h0, l0);
        split2(v0.z, v0.w, h1, l1);
        split2(v1.x, v1.y, h2, l2);
        split2(v1.z, v1.w, h3, l3);
        *(uint4*)(dhi + off) = make_uint4(h0, h1, h2, h3);
        *(uint4*)(dlo + off) = make_uint4(l0, l1, l2, l3);
    } else {
        const int gw = ((blockIdx.x - FSB) * blockDim.x + threadIdx.x) >> 5;
        const int L  = threadIdx.x & 31;
        const int i  = gw / (NN / 512);
        const int sp = gw % (NN / 512);
        const int cb = sp * 512 + L * 4;
        unsigned val[4];
#pragma unroll
        for (int k = 0; k < 4; k++) {
            const int c = cb + k * 128;
            const int4 v = *(const int4*)(adj + (size_t)i * NN + c);
            unsigned nib = ((v.x != 0 || c     == i) ? 1u : 0u)
                         | ((v.y != 0 || c + 1 == i) ? 2u : 0u)
                         | ((v.z != 0 || c + 2 == i) ? 4u : 0u)
                         | ((v.w != 0 || c + 3 == i) ? 8u : 0u);
            val[k] = nib << ((L & 7) * 4);
        }
#pragma unroll
        for (int k = 0; k < 4; k++) {
            val[k] |= __shfl_xor_sync(0xffffffffu, val[k], 1);
            val[k] |= __shfl_xor_sync(0xffffffffu, val[k], 2);
            val[k] |= __shfl_xor_sync(0xffffffffu, val[k], 4);
        }
        if ((L & 7) == 0) {
            const int base = i * MW + sp * 16 + (L >> 3);
#pragma unroll
            for (int k = 0; k < 4; k++) g_mask[base + k * 4] = val[k];
        }
    }
}

// ---------------- Kernel 1: g_h = X @ W^T (bf16-split HMMA, 1 sync/iter) ----------------
__global__ __launch_bounds__(384) void gemm_kernel() {
    __shared__ __align__(16) unsigned char Ah[2][96 * 64];
    __shared__ __align__(16) unsigned char Al[2][96 * 64];
    __shared__ __align__(16) unsigned char Bh[2][128 * 64];
    __shared__ __align__(16) unsigned char Bl[2][128 * 64];

    const int tid = threadIdx.x;
    const int w   = tid >> 5;
    const int L   = tid & 31;
    const int bm  = blockIdx.x * 96;
    const int bn  = blockIdx.y * 128;

    const int arow   = tid >> 2;
    const int achunk = tid & 3;
    const uint32_t aoff = (uint32_t)(arow * 64 + ((achunk ^ ((arow >> 1) & 3)) << 4));
    const int brow0  = tid >> 2;
    const int bchunk = tid & 3;
    const uint32_t boff0 = (uint32_t)(brow0 * 64 + ((bchunk ^ ((brow0 >> 1) & 3)) << 4));
    const int brow1  = 96 + (tid >> 2);
    const uint32_t boff1 = (uint32_t)(brow1 * 64 + ((bchunk ^ ((brow1 >> 1) & 3)) << 4));
    const bool hasB1 = tid < 128;

    const int warp_m = (w >> 2) * 32;
    const int warp_n = (w & 3) * 32;

    float acc[2][4][4];
#pragma unroll
    for (int mg = 0; mg < 2; mg++)
#pragma unroll
        for (int ng = 0; ng < 4; ng++)
#pragma unroll
            for (int k = 0; k < 4; k++) acc[mg][ng][k] = 0.f;

    uint4 xa_h, xa_l, wb_h0, wb_l0, wb_h1, wb_l1;
    {
        const size_t ao = (size_t)(bm + arow) * INF + achunk * 8;
        xa_h = *(const uint4*)(g_X1 + ao);
        xa_l = *(const uint4*)(g_X2 + ao);
        const size_t bo0 = (size_t)(bn + brow0) * INF + bchunk * 8;
        wb_h0 = *(const uint4*)(g_W1 + bo0);
        wb_l0 = *(const uint4*)(g_W2 + bo0);
        if (hasB1) {
            const size_t bo1 = (size_t)(bn + brow1) * INF + bchunk * 8;
            wb_h1 = *(const uint4*)(g_W1 + bo1);
            wb_l1 = *(const uint4*)(g_W2 + bo1);
        }
        *(uint4*)&Ah[0][aoff]  = xa_h;
        *(uint4*)&Al[0][aoff]  = xa_l;
        *(uint4*)&Bh[0][boff0] = wb_h0;
        *(uint4*)&Bl[0][boff0] = wb_l0;
        if (hasB1) {
            *(uint4*)&Bh[0][boff1] = wb_h1;
            *(uint4*)&Bl[0][boff1] = wb_l1;
        }
        const size_t ao1 = ao + 32;
        xa_h = *(const uint4*)(g_X1 + ao1);
        xa_l = *(const uint4*)(g_X2 + ao1);
        wb_h0 = *(const uint4*)(g_W1 + bo0 + 32);
        wb_l0 = *(const uint4*)(g_W2 + bo0 + 32);
        if (hasB1) {
            const size_t bo1 = (size_t)(bn + brow1) * INF + bchunk * 8 + 32;
            wb_h1 = *(const uint4*)(g_W1 + bo1);
            wb_l1 = *(const uint4*)(g_W2 + bo1);
        }
    }
    __syncthreads();

    for (int it = 0; it < INF / 32; it++) {
        const int buf = it & 1;
        const int nbuf = buf ^ 1;

        const uint32_t aAh = smem_u32(&Ah[buf][0]);
        const uint32_t aAl = smem_u32(&Al[buf][0]);
        const uint32_t aBh = smem_u32(&Bh[buf][0]);
        const uint32_t aBl = smem_u32(&Bl[buf][0]);

        uint32_t bh[4][4], bl[4][4];
#pragma unroll
        for (int ng = 0; ng < 4; ng++) {
            const int row = warp_n + ng * 8 + (L & 7);
            const int ch  = L >> 3;
            const uint32_t off = (uint32_t)(row * 64 + ((ch ^ ((row >> 1) & 3)) << 4));
            ldmx4(bh[ng], aBh + off);
            ldmx4(bl[ng], aBl + off);
        }
        uint32_t ah[2][2][4], al[2][2][4];
#pragma unroll
        for (int mg = 0; mg < 2; mg++)
#pragma unroll
            for (int ks = 0; ks < 2; ks++) {
                const int mat = L >> 3;
                const int row = warp_m + mg * 16 + (L & 7) + (mat & 1) * 8;
                const int ch  = ks * 2 + (mat >> 1);
                const uint32_t off = (uint32_t)(row * 64 + ((ch ^ ((row >> 1) & 3)) << 4));
                ldmx4(ah[mg][ks], aAh + off);
                ldmx4(al[mg][ks], aAl + off);
            }

        if (it + 1 < INF / 32) {
            *(uint4*)&Ah[nbuf][aoff]  = xa_h;
            *(uint4*)&Al[nbuf][aoff]  = xa_l;
            *(uint4*)&Bh[nbuf][boff0] = wb_h0;
            *(uint4*)&Bl[nbuf][boff0] = wb_l0;
            if (hasB1) {
                *(uint4*)&Bh[nbuf][boff1] = wb_h1;
                *(uint4*)&Bl[nbuf][boff1] = wb_l1;
            }
        }
        if (it + 2 < INF / 32) {
            const int k0 = (it + 2) * 32;
            const size_t ao = (size_t)(bm + arow) * INF + k0 + achunk * 8;
            xa_h = *(const uint4*)(g_X1 + ao);
            xa_l = *(const uint4*)(g_X2 + ao);
            const size_t bo0 = (size_t)(bn + brow0) * INF + k0 + bchunk * 8;
            wb_h0 = *(const uint4*)(g_W1 + bo0);
            wb_l0 = *(const uint4*)(g_W2 + bo0);
            if (hasB1) {
                const size_t bo1 = (size_t)(bn + brow1) * INF + k0 + bchunk * 8;
                wb_h1 = *(const uint4*)(g_W1 + bo1);
                wb_l1 = *(const uint4*)(g_W2 + bo1);
            }
        }

#pragma unroll
        for (int mg = 0; mg < 2; mg++)
#pragma unroll
            for (int ng = 0; ng < 4; ng++)
#pragma unroll
                for (int ks = 0; ks < 2; ks++) {
                    mma_bf16(acc[mg][ng], ah[mg][ks], bh[ng][2*ks], bh[ng][2*ks+1]);
                    mma_bf16(acc[mg][ng], ah[mg][ks], bl[ng][2*ks], bl[ng][2*ks+1]);
                    mma_bf16(acc[mg][ng], al[mg][ks], bh[ng][2*ks], bh[ng][2*ks+1]);
                }
        __syncthreads();
    }

#pragma unroll
    for (int mg = 0; mg < 2; mg++)
#pragma unroll
        for (int ng = 0; ng < 4; ng++) {
            const int row = bm + warp_m + mg * 16 + (L >> 2);
            const int col = bn + warp_n + ng * 8 + (L & 3) * 2;
            *(float2*)(g_h + (size_t)row * OF + col)       = make_float2(acc[mg][ng][0], acc[mg][ng][1]);
            *(float2*)(g_h + (size_t)(row + 8) * OF + col) = make_float2(acc[mg][ng][2], acc[mg][ng][3]);
        }
}

// ---------------- Kernel 3b: fused transpose(fp16) + coef + per-head max, 2 tiles/block ----------------
__global__ __launch_bounds__(256) void htrans_kernel(const float* __restrict__ a_src,
                                                     const float* __restrict__ a_dst) {
    __shared__ float tl[2][32][65];
    const int h  = blockIdx.y;
    const int n0 = blockIdx.x * 64;
    const int t  = threadIdx.x;
    const int r  = t >> 3;
    const int c8 = (t & 7) * 8;
    {
        const float* s0 = g_h + (size_t)(n0 + r) * OF + h * HD + c8;
        const float* s1 = g_h + (size_t)(n0 + 32 + r) * OF + h * HD + c8;
        float4 u0 = *(const float4*)s0;
        float4 u1 = *(const float4*)(s0 + 4);
        float4 w0 = *(const float4*)s1;
        float4 w1 = *(const float4*)(s1 + 4);
        tl[0][r][c8+0] = u0.x; tl[0][r][c8+1] = u0.y; tl[0][r][c8+2] = u0.z; tl[0][r][c8+3] = u0.w;
        tl[0][r][c8+4] = u1.x; tl[0][r][c8+5] = u1.y; tl[0][r][c8+6] = u1.z; tl[0][r][c8+7] = u1.w;
        tl[1][r][c8+0] = w0.x; tl[1][r][c8+1] = w0.y; tl[1][r][c8+2] = w0.z; tl[1][r][c8+3] = w0.w;
        tl[1][r][c8+4] = w1.x; tl[1][r][c8+5] = w1.y; tl[1][r][c8+6] = w1.z; tl[1][r][c8+7] = w1.w;

        const float4* as = (const float4*)(a_src + h * HD + c8);
        const float4* ad = (const float4*)(a_dst + h * HD + c8);
        float4 a0 = as[0], a1 = as[1], d0 = ad[0], d1 = ad[1];
        float s0d = u0.x*a0.x + u0.y*a0.y + u0.z*a0.z + u0.w*a0.w
                  + u1.x*a1.x + u1.y*a1.y + u1.z*a1.z + u1.w*a1.w;
        float t0d = u0.x*d0.x + u0.y*d0.y + u0.z*d0.z + u0.w*d0.w
                  + u1.x*d1.x + u1.y*d1.y + u1.z*d1.z + u1.w*d1.w;
        float s1d = w0.x*a0.x + w0.y*a0.y + w0.z*a0.z + w0.w*a0.w
                  + w1.x*a1.x + w1.y*a1.y + w1.z*a1.z + w1.w*a1.w;
        float t1d = w0.x*d0.x + w0.y*d0.y + w0.z*d0.z + w0.w*d0.w
                  + w1.x*d1.x + w1.y*d1.y + w1.z*d1.z + w1.w*d1.w;
#pragma unroll
        for (int o = 1; o <= 4; o <<= 1) {
            s0d += __shfl_xor_sync(0xffffffffu, s0d, o);
            t0d += __shfl_xor_sync(0xffffffffu, t0d, o);
            s1d += __shfl_xor_sync(0xffffffffu, s1d, o);
            t1d += __shfl_xor_sync(0xffffffffu, t1d, o);
        }
        float Qc = 0.f, qc = 0.f;
        if ((t & 7) == 0) {
            const int i0 = h * NN + n0 + r;
            const int i1 = i0 + 32;
            const float Q0 = __expf(t0d), q0 = __expf(0.2f * t0d);
            const float Q1 = __expf(t1d), q1 = __expf(0.2f * t1d);
            g_P[i0] = __expf(s0d);
            g_p[i0] = __expf(0.2f * s0d);
            g_Q[i0] = Q0;
            g_q[i0] = q0;
            g_P[i1] = __expf(s1d);
            g_p[i1] = __expf(0.2f * s1d);
            g_Q[i1] = Q1;
            g_q[i1] = q1;
            Qc = fmaxf(Q0, Q1);
            qc = fmaxf(q0, q1);
        }
        Qc = fmaxf(Qc, __shfl_xor_sync(0xffffffffu, Qc, 8));
        qc = fmaxf(qc, __shfl_xor_sync(0xffffffffu, qc, 8));
        Qc = fmaxf(Qc, __shfl_xor_sync(0xffffffffu, Qc, 16));
        qc = fmaxf(qc, __shfl_xor_sync(0xffffffffu, qc, 16));
        if ((t & 31) == 0) {
            atomicMax(&g_QmU[h], __float_as_uint(Qc));
            atomicMax(&g_qmU[h], __float_as_uint(qc));
        }
    }
    __syncthreads();
    const int d  = t >> 2;
    const int ns = (t & 3) * 8;
    uint32_t o0[4], o1[4];
#pragma unroll
    for (int k = 0; k < 4; k++) {
        o0[k] = packh2(tl[0][ns + 2*k + 1][d], tl[0][ns + 2*k][d]);
        o1[k] = packh2(tl[1][ns + 2*k + 1][d], tl[1][ns + 2*k][d]);
    }
    const size_t ob = (size_t)(h * HD + d) * NN + n0 + ns;
    *(uint4*)(g_hTh + ob)      = make_uint4(o0[0], o0[1], o0[2], o0[3]);
    *(uint4*)(g_hTh + ob + 32) = make_uint4(o1[0], o1[1], o1[2], o1[3]);
}

// ---------------- Kernel 4: fp16 MMA softmax-aggregate, KT=128, j-split warps ----------------
// CTA = 192 i x 1 head, 12 warps = 6 i-ranges x 2 j-halves (64 j each = 2 sub-tiles).
__global__ __launch_bounds__(384) void attn_kernel(float* __restrict__ out) {
    __shared__ __align__(16) unsigned char Bsm[2][4][HD * 64];  // [buf][subtile] 4KB each
    __shared__ __align__(8)  float2 QQ[2][KT4];
    __shared__ float zsh[2][MT];

    const int tid  = threadIdx.x;
    const int w    = tid >> 5;
    const int L    = tid & 31;
    const int head = blockIdx.y;
    const int i0   = blockIdx.x * MT;

    const int ir = w % 6;
    const int jh = w / 6;

    const bool stager = tid < 256;
    const int sd = (tid >> 2) & 63;
    const int q4 = tid & 3;
    const __half* hp = g_hTh + (size_t)(head * HD + sd) * NN;
    const int skey = sd & 3;
    const int ppos = q4 * 4;

    const int gr = L >> 2;
    const int c  = L & 3;
    const int rbase = i0 + ir * 32;
    const float Qm = __uint_as_float(g_QmU[head]);
    const float qm = __uint_as_float(g_qmU[head]);
    float Ps[4], ps[4];
    const unsigned* mp[4];
#pragma unroll
    for (int k = 0; k < 4; k++) {
        const int r = rbase + gr + k * 8;
        const float Pr = g_P[head * NN + r];
        const float pr = g_p[head * NN + r];
        const float sc = 1.0f / (Pr * Qm + pr * qm);
        Ps[k] = Pr * sc;
        ps[k] = pr * sc;
        mp[k] = g_mask + (size_t)r * MW;
    }

    const uint32_t ONE2 = 0x3C003C00u;

    float acc[2][8][4];
#pragma unroll
    for (int mg = 0; mg < 2; mg++)
#pragma unroll
        for (int n = 0; n < 8; n++)
#pragma unroll
            for (int k = 0; k < 4; k++) acc[mg][n][k] = 0.f;
    float zacc[2][4] = {{0.f,0.f,0.f,0.f},{0.f,0.f,0.f,0.f}};

    // ---- prologue: stage tile0 (4 sub-tiles), prefetch tile1 ----
    uint4 pv[4];
    if (stager) {
#pragma unroll
        for (int q = 0; q < 4; q++) {
            uint4 v = *(const uint4*)(hp + q * 32 + q4 * 8);
            unsigned char* b = &Bsm[0][q][sd * 64];
            *(uint32_t*)(b + (((0 ^ skey) << 4) + ppos)) = v.x;
            *(uint32_t*)(b + (((1 ^ skey) << 4) + ppos)) = v.y;
            *(uint32_t*)(b + (((2 ^ skey) << 4) + ppos)) = v.z;
            *(uint32_t*)(b + (((3 ^ skey) << 4) + ppos)) = v.w;
        }
#pragma unroll
        for (int q = 0; q < 4; q++)
            pv[q] = *(const uint4*)(hp + KT4 + q * 32 + q4 * 8);
    }
    if (tid < KT4)
        QQ[0][tid] = make_float2(g_Q[head * NN + tid], g_q[head * NN + tid]);
    unsigned cm[4][2], nm[4][2];
#pragma unroll
    for (int k = 0; k < 4; k++)
#pragma unroll
        for (int s = 0; s < 2; s++) {
            cm[k][s] = mp[k][jh * 2 + s];
            nm[k][s] = mp[k][4 + jh * 2 + s];
        }
    float nQ = 0.f, nq = 0.f;
    if (tid < KT4) {
        nQ = g_Q[head * NN + KT4 + tid];
        nq = g_q[head * NN + KT4 + tid];
    }
    __syncthreads();

    for (int t = 0; t < NT4; t++) {
        const int buf = t & 1;
        const int nbuf = buf ^ 1;

        // store prefetched tile t+1
        if (t + 1 < NT4) {
            if (stager) {
#pragma unroll
                for (int q = 0; q < 4; q++) {
                    unsigned char* b = &Bsm[nbuf][q][sd * 64];
                    *(uint32_t*)(b + (((0 ^ skey) << 4) + ppos)) = pv[q].x;
                    *(uint32_t*)(b + (((1 ^ skey) << 4) + ppos)) = pv[q].y;
                    *(uint32_t*)(b + (((2 ^ skey) << 4) + ppos)) = pv[q].z;
                    *(uint32_t*)(b + (((3 ^ skey) << 4) + ppos)) = pv[q].w;
                }
            }
            if (tid < KT4) QQ[nbuf][tid] = make_float2(nQ, nq);
        }

        // ---- per sub-tile: A-gen then MMA (keeps A live range short) ----
#pragma unroll
        for (int sub = 0; sub < 2; sub++) {
            uint32_t A[2][2][4];
#pragma unroll
            for (int mg = 0; mg < 2; mg++) {
                const unsigned ma = cm[2 * mg][sub];
                const unsigned mb = cm[2 * mg + 1][sub];
                const float Pa = Ps[2 * mg], pa = ps[2 * mg];
                const float Pb = Ps[2 * mg + 1], pb = ps[2 * mg + 1];
#pragma unroll
                for (int s = 0; s < 2; s++) {
                    const int ja = 16 * s + 2 * c;
                    const int jq = jh * 64 + sub * 32 + ja;
                    float2 qa0 = QQ[buf][jq];
                    float2 qa1 = QQ[buf][jq + 1];
                    float2 qb0 = QQ[buf][jq + 8];
                    float2 qb1 = QQ[buf][jq + 9];
                    float wa0 = fmaxf(Pa * qa0.x, pa * qa0.y); wa0 = ((ma >> ja)       & 1u) ? wa0 : 0.f;
                    float wa1 = fmaxf(Pa * qa1.x, pa * qa1.y); wa1 = ((ma >> (ja + 1)) & 1u) ? wa1 : 0.f;
                    float wa8 = fmaxf(Pa * qb0.x, pa * qb0.y); wa8 = ((ma >> (ja + 8)) & 1u) ? wa8 : 0.f;
                    float wa9 = fmaxf(Pa * qb1.x, pa * qb1.y); wa9 = ((ma >> (ja + 9)) & 1u) ? wa9 : 0.f;
                    float wb0 = fmaxf(Pb * qa0.x, pb * qa0.y); wb0 = ((mb >> ja)       & 1u) ? wb0 : 0.f;
                    float wb1 = fmaxf(Pb * qa1.x, pb * qa1.y); wb1 = ((mb >> (ja + 1)) & 1u) ? wb1 : 0.f;
                    float wb8 = fmaxf(Pb * qb0.x, pb * qb0.y); wb8 = ((mb >> (ja + 8)) & 1u) ? wb8 : 0.f;
                    float wb9 = fmaxf(Pb * qb1.x, pb * qb1.y); wb9 = ((mb >> (ja + 9)) & 1u) ? wb9 : 0.f;
                    A[mg][s][0] = packh2(wa1, wa0);
                    A[mg][s][1] = packh2(wb1, wb0);
                    A[mg][s][2] = packh2(wa9, wa8);
                    A[mg][s][3] = packh2(wb9, wb8);
                }
            }
            const int st = jh * 2 + sub;
#pragma unroll
            for (int nt = 0; nt < 8; nt++) {
                const int d = nt * 8 + gr;
                const uint32_t off = (uint32_t)(d * 64 + ((c ^ (gr & 3)) << 4));
                uint4 v = *(const uint4*)(&Bsm[buf][st][off]);
                mma_f16(acc[0][nt], A[0][0], v.x, v.y);
                mma_f16(acc[0][nt], A[0][1], v.z, v.w);
                mma_f16(acc[1][nt], A[1][0], v.x, v.y);
                mma_f16(acc[1][nt], A[1][1], v.z, v.w);
            }
            mma_f16(zacc[0], A[0][0], ONE2, ONE2);
            mma_f16(zacc[0], A[0][1], ONE2, ONE2);
            mma_f16(zacc[1], A[1][0], ONE2, ONE2);
            mma_f16(zacc[1], A[1][1], ONE2, ONE2);
        }

        // rotate masks, prefetch tile t+2
#pragma unroll
        for (int k = 0; k < 4; k++) {
            cm[k][0] = nm[k][0];
            cm[k][1] = nm[k][1];
        }
        if (t + 2 < NT4) {
            const int j0 = (t + 2) * KT4;
            if (stager) {
#pragma unroll
                for (int q = 0; q < 4; q++)
                    pv[q] = *(const uint4*)(hp + j0 + q * 32 + q4 * 8);
            }
#pragma unroll
            for (int k = 0; k < 4; k++)
#pragma unroll
                for (int s = 0; s < 2; s++)
                    nm[k][s] = mp[k][4 * (t + 2) + jh * 2 + s];
            if (tid < KT4) {
                nQ = g_Q[head * NN + j0 + tid];
                nq = g_q[head * NN + j0 + tid];
            }
        }
        __syncthreads();
    }

    // ---- combine the two j-halves ----
#pragma unroll
    for (int mg = 0; mg < 2; mg++) {
        const int la = ir * 32 + mg * 16 + gr;
        zsh[jh][la]     = zacc[mg][0];
        zsh[jh][la + 8] = zacc[mg][2];
    }
    __syncthreads();
    const int cb = c * 2;
    if (jh == 1) {
#pragma unroll
        for (int mg = 0; mg < 2; mg++) {
            const int la = ir * 32 + mg * 16 + gr;
            const float iz0 = 1.0f / (zacc[mg][0] + zsh[0][la]);
            const float iz1 = 1.0f / (zacc[mg][2] + zsh[0][la + 8]);
            float* o0 = out + (size_t)(i0 + la) * OF + head * HD + cb;
            float* o1 = o0 + 8 * OF;
#pragma unroll
            for (int nt = 0; nt < 8; nt++) {
                *(float2*)(o0 + nt * 8) = make_float2(acc[mg][nt][0] * iz0, acc[mg][nt][1] * iz0);
                *(float2*)(o1 + nt * 8) = make_float2(acc[mg][nt][2] * iz1, acc[mg][nt][3] * iz1);
            }
        }
    }
    __syncthreads();
    if (jh == 0) {
#pragma unroll
        for (int mg = 0; mg < 2; mg++) {
            const int la = ir * 32 + mg * 16 + gr;
            const float iz0 = 1.0f / (zacc[mg][0] + zsh[1][la]);
            const float iz1 = 1.0f / (zacc[mg][2] + zsh[1][la + 8]);
            float* o0 = out + (size_t)(i0 + la) * OF + head * HD + cb;
            float* o1 = o0 + 8 * OF;
#pragma unroll
            for (int nt = 0; nt < 8; nt++) {
                float2 v0 = *(float2*)(o0 + nt * 8);
                float2 v1 = *(float2*)(o1 + nt * 8);
                v0.x += acc[mg][nt][0] * iz0; v0.y += acc[mg][nt][1] * iz0;
                v1.x += acc[mg][nt][2] * iz1; v1.y += acc[mg][nt][3] * iz1;
                *(float2*)(o0 + nt * 8) = v0;
                *(float2*)(o1 + nt * 8) = v1;
            }
        }
    }
}

// ---------------- launch ----------------
extern "C" void kernel_launch(void* const* d_in, const int* in_sizes, int n_in,
                              void* d_out, int out_size) {
    const float* x     = (const float*)d_in[0];
    const int*   adj   = (const int*)d_in[1];
    const float* W     = (const float*)d_in[2];
    const float* a_src = (const float*)d_in[3];
    const float* a_dst = (const float*)d_in[4];
    float* out = (float*)d_out;

    const int mask_blocks = (NN * (NN / 512) * 32) / 256;   // 2304
    prep_kernel<<<FSB + mask_blocks, 256>>>(x, W, adj);
    gemm_kernel<<<dim3(NN / 96, OF / 128), 384>>>();
    htrans_kernel<<<dim3(NN / 64, NH), 256>>>(a_src, a_dst);
    attn_kernel<<<dim3(NN / MT, NH), 384>>>(out);
}

// round 16
// speedup vs baseline: 1.3734x; 1.3734x over previous
#include <cuda_runtime.h>
#include <cuda_bf16.h>
#include <cuda_fp16.h>
#include <cstdint>

#define NN   3072
#define INF  512
#define NH   8
#define HD   64
#define OF   512   // NH*HD
#define MW   96    // mask words per row
#define KT2  64    // attn j double-tile
#define MT   192   // attn i tile per CTA (6 i-ranges x 32 i)
#define NT2  (NN / KT2)
#define FSB  (((NN + OF) * INF) / 2048)   // fsplit blocks in prep_kernel

// ---------------- scratch ----------------
__device__ float         g_h[NN * OF];
__device__ float         g_P[NH * NN];
__device__ float         g_p[NH * NN];
__device__ float         g_Q[NH * NN];
__device__ float         g_q[NH * NN];
__device__ unsigned      g_QmU[NH];
__device__ unsigned      g_qmU[NH];
__device__ unsigned      g_mask[NN * MW];
__device__ __half        g_hTh[NH * HD * NN];      // [h][d][n], fp16 h (transposed)
__device__ __nv_bfloat16 g_X1[NN * INF];
__device__ __nv_bfloat16 g_X2[NN * INF];
__device__ __nv_bfloat16 g_W1[OF * INF];
__device__ __nv_bfloat16 g_W2[OF * INF];

__device__ __forceinline__ uint32_t smem_u32(const void* p) {
    uint32_t a;
    asm("{ .reg .u64 t; cvta.to.shared.u64 t, %1; cvt.u32.u64 %0, t; }" : "=r"(a) : "l"(p));
    return a;
}

__device__ __forceinline__ void mma_bf16(float* c, const uint32_t* a, uint32_t b0, uint32_t b1) {
    asm volatile(
        "mma.sync.aligned.m16n8k16.row.col.f32.bf16.bf16.f32 "
        "{%0,%1,%2,%3}, {%4,%5,%6,%7}, {%8,%9}, {%0,%1,%2,%3};"
        : "+f"(c[0]), "+f"(c[1]), "+f"(c[2]), "+f"(c[3])
        : "r"(a[0]), "r"(a[1]), "r"(a[2]), "r"(a[3]), "r"(b0), "r"(b1));
}

__device__ __forceinline__ void mma_f16(float* c, const uint32_t* a, uint32_t b0, uint32_t b1) {
    asm volatile(
        "mma.sync.aligned.m16n8k16.row.col.f32.f16.f16.f32 "
        "{%0,%1,%2,%3}, {%4,%5,%6,%7}, {%8,%9}, {%0,%1,%2,%3};"
        : "+f"(c[0]), "+f"(c[1]), "+f"(c[2]), "+f"(c[3])
        : "r"(a[0]), "r"(a[1]), "r"(a[2]), "r"(a[3]), "r"(b0), "r"(b1));
}

__device__ __forceinline__ void ldmx4(uint32_t* r, uint32_t addr) {
    asm volatile("ldmatrix.sync.aligned.m8n8.x4.shared.b16 {%0,%1,%2,%3}, [%4];"
                 : "=r"(r[0]), "=r"(r[1]), "=r"(r[2]), "=r"(r[3]) : "r"(addr));
}

__device__ __forceinline__ void split2(float w0, float w1, uint32_t& hi, uint32_t& lo) {
    uint32_t h;
    asm("cvt.rn.bf16x2.f32 %0, %1, %2;" : "=r"(h) : "f"(w1), "f"(w0));
    float r0 = w0 - __uint_as_float(h << 16);
    float r1 = w1 - __uint_as_float(h & 0xffff0000u);
    uint32_t l;
    asm("cvt.rn.bf16x2.f32 %0, %1, %2;" : "=r"(l) : "f"(r1), "f"(r0));
    hi = h; lo = l;
}

__device__ __forceinline__ uint32_t packh2(float b, float a) {
    uint32_t r;
    asm("cvt.rn.f16x2.f32 %0, %1, %2;" : "=r"(r) : "f"(b), "f"(a));
    return r;
}

// ---------------- Kernel 0: fused fsplit (X,W -> bf16 hi/lo) + adjacency mask ----------------
__global__ __launch_bounds__(256) void prep_kernel(const float* __restrict__ x,
                                                   const float* __restrict__ Wm,
                                                   const int* __restrict__ adj) {
    if (blockIdx.x < FSB) {
        const int gidx = blockIdx.x * blockDim.x + threadIdx.x;
        if (blockIdx.x == 0 && threadIdx.x < 2 * NH) {
            if (threadIdx.x < NH) g_QmU[threadIdx.x] = 0u;
            else                  g_qmU[threadIdx.x - NH] = 0u;
        }
        const int idx = gidx * 8;
        const float* src;
        __nv_bfloat16 *dhi, *dlo;
        int off;
        if (idx < NN * INF) {
            src = x; dhi = g_X1; dlo = g_X2; off = idx;
        } else {
            src = Wm; dhi = g_W1; dlo = g_W2; off = idx - NN * INF;
        }
        float4 v0 = *(const float4*)(src + off);
        float4 v1 = *(const float4*)(src + off + 4);
        uint32_t h0, h1, h2, h3, l0, l1, l2, l3;
        split2(v0.x, v0.y, h0, l0);
        split2(v0.z, v0.w, h1, l1);
        split2(v1.x, v1.y, h2, l2);
        split2(v1.z, v1.w, h3, l3);
        *(uint4*)(dhi + off) = make_uint4(h0, h1, h2, h3);
        *(uint4*)(dlo + off) = make_uint4(l0, l1, l2, l3);
    } else {
        const int gw = ((blockIdx.x - FSB) * blockDim.x + threadIdx.x) >> 5;
        const int L  = threadIdx.x & 31;
        const int i  = gw / (NN / 512);
        const int sp = gw % (NN / 512);
        const int cb = sp * 512 + L * 4;
        unsigned val[4];
#pragma unroll
        for (int k = 0; k < 4; k++) {
            const int c = cb + k * 128;
            const int4 v = *(const int4*)(adj + (size_t)i * NN + c);
            unsigned nib = ((v.x != 0 || c     == i) ? 1u : 0u)
                         | ((v.y != 0 || c + 1 == i) ? 2u : 0u)
                         | ((v.z != 0 || c + 2 == i) ? 4u : 0u)
                         | ((v.w != 0 || c + 3 == i) ? 8u : 0u);
            val[k] = nib << ((L & 7) * 4);
        }
#pragma unroll
        for (int k = 0; k < 4; k++) {
            val[k] |= __shfl_xor_sync(0xffffffffu, val[k], 1);
            val[k] |= __shfl_xor_sync(0xffffffffu, val[k], 2);
            val[k] |= __shfl_xor_sync(0xffffffffu, val[k], 4);
        }
        if ((L & 7) == 0) {
            const int base = i * MW + sp * 16 + (L >> 3);
#pragma unroll
            for (int k = 0; k < 4; k++) g_mask[base + k * 4] = val[k];
        }
    }
}

// ---------------- Kernel 1: g_h = X @ W^T (bf16-split HMMA, 1 sync/iter) ----------------
__global__ __launch_bounds__(384) void gemm_kernel() {
    __shared__ __align__(16) unsigned char Ah[2][96 * 64];
    __shared__ __align__(16) unsigned char Al[2][96 * 64];
    __shared__ __align__(16) unsigned char Bh[2][128 * 64];
    __shared__ __align__(16) unsigned char Bl[2][128 * 64];

    const int tid = threadIdx.x;
    const int w   = tid >> 5;
    const int L   = tid & 31;
    const int bm  = blockIdx.x * 96;
    const int bn  = blockIdx.y * 128;

    const int arow   = tid >> 2;
    const int achunk = tid & 3;
    const uint32_t aoff = (uint32_t)(arow * 64 + ((achunk ^ ((arow >> 1) & 3)) << 4));
    const int brow0  = tid >> 2;
    const int bchunk = tid & 3;
    const uint32_t boff0 = (uint32_t)(brow0 * 64 + ((bchunk ^ ((brow0 >> 1) & 3)) << 4));
    const int brow1  = 96 + (tid >> 2);
    const uint32_t boff1 = (uint32_t)(brow1 * 64 + ((bchunk ^ ((brow1 >> 1) & 3)) << 4));
    const bool hasB1 = tid < 128;

    const int warp_m = (w >> 2) * 32;
    const int warp_n = (w & 3) * 32;

    float acc[2][4][4];
#pragma unroll
    for (int mg = 0; mg < 2; mg++)
#pragma unroll
        for (int ng = 0; ng < 4; ng++)
#pragma unroll
            for (int k = 0; k < 4; k++) acc[mg][ng][k] = 0.f;

    uint4 xa_h, xa_l, wb_h0, wb_l0, wb_h1, wb_l1;
    {
        const size_t ao = (size_t)(bm + arow) * INF + achunk * 8;
        xa_h = *(const uint4*)(g_X1 + ao);
        xa_l = *(const uint4*)(g_X2 + ao);
        const size_t bo0 = (size_t)(bn + brow0) * INF + bchunk * 8;
        wb_h0 = *(const uint4*)(g_W1 + bo0);
        wb_l0 = *(const uint4*)(g_W2 + bo0);
        if (hasB1) {
            const size_t bo1 = (size_t)(bn + brow1) * INF + bchunk * 8;
            wb_h1 = *(const uint4*)(g_W1 + bo1);
            wb_l1 = *(const uint4*)(g_W2 + bo1);
        }
        *(uint4*)&Ah[0][aoff]  = xa_h;
        *(uint4*)&Al[0][aoff]  = xa_l;
        *(uint4*)&Bh[0][boff0] = wb_h0;
        *(uint4*)&Bl[0][boff0] = wb_l0;
        if (hasB1) {
            *(uint4*)&Bh[0][boff1] = wb_h1;
            *(uint4*)&Bl[0][boff1] = wb_l1;
        }
        const size_t ao1 = ao + 32;
        xa_h = *(const uint4*)(g_X1 + ao1);
        xa_l = *(const uint4*)(g_X2 + ao1);
        wb_h0 = *(const uint4*)(g_W1 + bo0 + 32);
        wb_l0 = *(const uint4*)(g_W2 + bo0 + 32);
        if (hasB1) {
            const size_t bo1 = (size_t)(bn + brow1) * INF + bchunk * 8 + 32;
            wb_h1 = *(const uint4*)(g_W1 + bo1);
            wb_l1 = *(const uint4*)(g_W2 + bo1);
        }
    }
    __syncthreads();

    for (int it = 0; it < INF / 32; it++) {
        const int buf = it & 1;
        const int nbuf = buf ^ 1;

        const uint32_t aAh = smem_u32(&Ah[buf][0]);
        const uint32_t aAl = smem_u32(&Al[buf][0]);
        const uint32_t aBh = smem_u32(&Bh[buf][0]);
        const uint32_t aBl = smem_u32(&Bl[buf][0]);

        uint32_t bh[4][4], bl[4][4];
#pragma unroll
        for (int ng = 0; ng < 4; ng++) {
            const int row = warp_n + ng * 8 + (L & 7);
            const int ch  = L >> 3;
            const uint32_t off = (uint32_t)(row * 64 + ((ch ^ ((row >> 1) & 3)) << 4));
            ldmx4(bh[ng], aBh + off);
            ldmx4(bl[ng], aBl + off);
        }
        uint32_t ah[2][2][4], al[2][2][4];
#pragma unroll
        for (int mg = 0; mg < 2; mg++)
#pragma unroll
            for (int ks = 0; ks < 2; ks++) {
                const int mat = L >> 3;
                const int row = warp_m + mg * 16 + (L & 7) + (mat & 1) * 8;
                const int ch  = ks * 2 + (mat >> 1);
                const uint32_t off = (uint32_t)(row * 64 + ((ch ^ ((row >> 1) & 3)) << 4));
                ldmx4(ah[mg][ks], aAh + off);
                ldmx4(al[mg][ks], aAl + off);
            }

        if (it + 1 < INF / 32) {
            *(uint4*)&Ah[nbuf][aoff]  = xa_h;
            *(uint4*)&Al[nbuf][aoff]  = xa_l;
            *(uint4*)&Bh[nbuf][boff0] = wb_h0;
            *(uint4*)&Bl[nbuf][boff0] = wb_l0;
            if (hasB1) {
                *(uint4*)&Bh[nbuf][boff1] = wb_h1;
                *(uint4*)&Bl[nbuf][boff1] = wb_l1;
            }
        }
        if (it + 2 < INF / 32) {
            const int k0 = (it + 2) * 32;
            const size_t ao = (size_t)(bm + arow) * INF + k0 + achunk * 8;
            xa_h = *(const uint4*)(g_X1 + ao);
            xa_l = *(const uint4*)(g_X2 + ao);
            const size_t bo0 = (size_t)(bn + brow0) * INF + k0 + bchunk * 8;
            wb_h0 = *(const uint4*)(g_W1 + bo0);
            wb_l0 = *(const uint4*)(g_W2 + bo0);
            if (hasB1) {
                const size_t bo1 = (size_t)(bn + brow1) * INF + k0 + bchunk * 8;
                wb_h1 = *(const uint4*)(g_W1 + bo1);
                wb_l1 = *(const uint4*)(g_W2 + bo1);
            }
        }

#pragma unroll
        for (int mg = 0; mg < 2; mg++)
#pragma unroll
            for (int ng = 0; ng < 4; ng++)
#pragma unroll
                for (int ks = 0; ks < 2; ks++) {
                    mma_bf16(acc[mg][ng], ah[mg][ks], bh[ng][2*ks], bh[ng][2*ks+1]);
                    mma_bf16(acc[mg][ng], ah[mg][ks], bl[ng][2*ks], bl[ng][2*ks+1]);
                    mma_bf16(acc[mg][ng], al[mg][ks], bh[ng][2*ks], bh[ng][2*ks+1]);
                }
        __syncthreads();
    }

#pragma unroll
    for (int mg = 0; mg < 2; mg++)
#pragma unroll
        for (int ng = 0; ng < 4; ng++) {
            const int row = bm + warp_m + mg * 16 + (L >> 2);
            const int col = bn + warp_n + ng * 8 + (L & 3) * 2;
            *(float2*)(g_h + (size_t)row * OF + col)       = make_float2(acc[mg][ng][0], acc[mg][ng][1]);
            *(float2*)(g_h + (size_t)(row + 8) * OF + col) = make_float2(acc[mg][ng][2], acc[mg][ng][3]);
        }
}

// ---------------- Kernel 3b: fused transpose(fp16) + coef + per-head max, 2 tiles/block ----------------
__global__ __launch_bounds__(256) void htrans_kernel(const float* __restrict__ a_src,
                                                     const float* __restrict__ a_dst) {
    __shared__ float tl[2][32][65];
    const int h  = blockIdx.y;
    const int n0 = blockIdx.x * 64;
    const int t  = threadIdx.x;
    const int r  = t >> 3;
    const int c8 = (t & 7) * 8;
    {
        const float* s0 = g_h + (size_t)(n0 + r) * OF + h * HD + c8;
        const float* s1 = g_h + (size_t)(n0 + 32 + r) * OF + h * HD + c8;
        float4 u0 = *(const float4*)s0;
        float4 u1 = *(const float4*)(s0 + 4);
        float4 w0 = *(const float4*)s1;
        float4 w1 = *(const float4*)(s1 + 4);
        tl[0][r][c8+0] = u0.x; tl[0][r][c8+1] = u0.y; tl[0][r][c8+2] = u0.z; tl[0][r][c8+3] = u0.w;
        tl[0][r][c8+4] = u1.x; tl[0][r][c8+5] = u1.y; tl[0][r][c8+6] = u1.z; tl[0][r][c8+7] = u1.w;
        tl[1][r][c8+0] = w0.x; tl[1][r][c8+1] = w0.y; tl[1][r][c8+2] = w0.z; tl[1][r][c8+3] = w0.w;
        tl[1][r][c8+4] = w1.x; tl[1][r][c8+5] = w1.y; tl[1][r][c8+6] = w1.z; tl[1][r][c8+7] = w1.w;

        const float4* as = (const float4*)(a_src + h * HD + c8);
        const float4* ad = (const float4*)(a_dst + h * HD + c8);
        float4 a0 = as[0], a1 = as[1], d0 = ad[0], d1 = ad[1];
        float s0d = u0.x*a0.x + u0.y*a0.y + u0.z*a0.z + u0.w*a0.w
                  + u1.x*a1.x + u1.y*a1.y + u1.z*a1.z + u1.w*a1.w;
        float t0d = u0.x*d0.x + u0.y*d0.y + u0.z*d0.z + u0.w*d0.w
                  + u1.x*d1.x + u1.y*d1.y + u1.z*d1.z + u1.w*d1.w;
        float s1d = w0.x*a0.x + w0.y*a0.y + w0.z*a0.z + w0.w*a0.w
                  + w1.x*a1.x + w1.y*a1.y + w1.z*a1.z + w1.w*a1.w;
        float t1d = w0.x*d0.x + w0.y*d0.y + w0.z*d0.z + w0.w*d0.w
                  + w1.x*d1.x + w1.y*d1.y + w1.z*d1.z + w1.w*d1.w;
#pragma unroll
        for (int o = 1; o <= 4; o <<= 1) {
            s0d += __shfl_xor_sync(0xffffffffu, s0d, o);
            t0d += __shfl_xor_sync(0xffffffffu, t0d, o);
            s1d += __shfl_xor_sync(0xffffffffu, s1d, o);
            t1d += __shfl_xor_sync(0xffffffffu, t1d, o);
        }
        float Qc = 0.f, qc = 0.f;
        if ((t & 7) == 0) {
            const int i0 = h * NN + n0 + r;
            const int i1 = i0 + 32;
            const float Q0 = __expf(t0d), q0 = __expf(0.2f * t0d);
            const float Q1 = __expf(t1d), q1 = __expf(0.2f * t1d);
            g_P[i0] = __expf(s0d);
            g_p[i0] = __expf(0.2f * s0d);
            g_Q[i0] = Q0;
            g_q[i0] = q0;
            g_P[i1] = __expf(s1d);
            g_p[i1] = __expf(0.2f * s1d);
            g_Q[i1] = Q1;
            g_q[i1] = q1;
            Qc = fmaxf(Q0, Q1);
            qc = fmaxf(q0, q1);
        }
        Qc = fmaxf(Qc, __shfl_xor_sync(0xffffffffu, Qc, 8));
        qc = fmaxf(qc, __shfl_xor_sync(0xffffffffu, qc, 8));
        Qc = fmaxf(Qc, __shfl_xor_sync(0xffffffffu, Qc, 16));
        qc = fmaxf(qc, __shfl_xor_sync(0xffffffffu, qc, 16));
        if ((t & 31) == 0) {
            atomicMax(&g_QmU[h], __float_as_uint(Qc));
            atomicMax(&g_qmU[h], __float_as_uint(qc));
        }
    }
    __syncthreads();
    const int d  = t >> 2;
    const int ns = (t & 3) * 8;
    uint32_t o0[4], o1[4];
#pragma unroll
    for (int k = 0; k < 4; k++) {
        o0[k] = packh2(tl[0][ns + 2*k + 1][d], tl[0][ns + 2*k][d]);
        o1[k] = packh2(tl[1][ns + 2*k + 1][d], tl[1][ns + 2*k][d]);
    }
    const size_t ob = (size_t)(h * HD + d) * NN + n0 + ns;
    *(uint4*)(g_hTh + ob)      = make_uint4(o0[0], o0[1], o0[2], o0[3]);
    *(uint4*)(g_hTh + ob + 32) = make_uint4(o1[0], o1[1], o1[2], o1[3]);
}

// ---------------- Kernel 4: fp16 MMA softmax-aggregate, j-split warps (R14 version) ----------------
// CTA = 192 i x 1 head, 12 warps = 6 i-ranges (32 i) x 2 j-halves (32 j).
__global__ __launch_bounds__(384) void attn_kernel(float* __restrict__ out) {
    __shared__ __align__(16) unsigned char Bsm[2][2][HD * 64];  // [buf][half]
    __shared__ __align__(8)  float2 QQ[2][KT2];
    __shared__ float zsh[2][MT];

    const int tid  = threadIdx.x;
    const int w    = tid >> 5;
    const int L    = tid & 31;
    const int head = blockIdx.y;
    const int i0   = blockIdx.x * MT;

    const int ir = w % 6;            // i-range (32 rows)
    const int jh = w / 6;            // j-half

    const bool stager = tid < 256;
    const int sd = (tid >> 2) & 63;
    const int q4 = tid & 3;
    const __half* hp = g_hTh + (size_t)(head * HD + sd) * NN;
    const int skey = sd & 3;
    const int ppos = q4 * 4;

    const int gr = L >> 2;
    const int c  = L & 3;
    const int rbase = i0 + ir * 32;
    const float Qm = __uint_as_float(g_QmU[head]);
    const float qm = __uint_as_float(g_qmU[head]);
    float Ps[4], ps[4];
    const unsigned* mp[4];
#pragma unroll
    for (int k = 0; k < 4; k++) {
        const int r = rbase + gr + k * 8;
        const float Pr = g_P[head * NN + r];
        const float pr = g_p[head * NN + r];
        const float sc = 1.0f / (Pr * Qm + pr * qm);
        Ps[k] = Pr * sc;
        ps[k] = pr * sc;
        mp[k] = g_mask + (size_t)r * MW;
    }

    const uint32_t ONE2 = 0x3C003C00u;

    float acc[2][8][4];
#pragma unroll
    for (int mg = 0; mg < 2; mg++)
#pragma unroll
        for (int n = 0; n < 8; n++)
#pragma unroll
            for (int k = 0; k < 4; k++) acc[mg][n][k] = 0.f;
    float zacc[2][4] = {{0.f,0.f,0.f,0.f},{0.f,0.f,0.f,0.f}};

    // ---- prologue: stage tile0, prefetch tile1 ----
    uint4 nva, nvb;
    if (stager) {
        nva = *(const uint4*)(hp + q4 * 8);
        nvb = *(const uint4*)(hp + 32 + q4 * 8);
        unsigned char* ba = &Bsm[0][0][sd * 64];
        unsigned char* bb = &Bsm[0][1][sd * 64];
        *(uint32_t*)(ba + (((0 ^ skey) << 4) + ppos)) = nva.x;
        *(uint32_t*)(ba + (((1 ^ skey) << 4) + ppos)) = nva.y;
        *(uint32_t*)(ba + (((2 ^ skey) << 4) + ppos)) = nva.z;
        *(uint32_t*)(ba + (((3 ^ skey) << 4) + ppos)) = nva.w;
        *(uint32_t*)(bb + (((0 ^ skey) << 4) + ppos)) = nvb.x;
        *(uint32_t*)(bb + (((1 ^ skey) << 4) + ppos)) = nvb.y;
        *(uint32_t*)(bb + (((2 ^ skey) << 4) + ppos)) = nvb.z;
        *(uint32_t*)(bb + (((3 ^ skey) << 4) + ppos)) = nvb.w;
        nva = *(const uint4*)(hp + KT2 + q4 * 8);
        nvb = *(const uint4*)(hp + KT2 + 32 + q4 * 8);
    }
    if (tid < KT2)
        QQ[0][tid] = make_float2(g_Q[head * NN + tid], g_q[head * NN + tid]);
    unsigned cm[4], nm[4];
#pragma unroll
    for (int k = 0; k < 4; k++) {
        cm[k] = mp[k][jh];
        nm[k] = mp[k][2 + jh];
    }
    float nQ = 0.f, nq = 0.f;
    if (tid < KT2) {
        nQ = g_Q[head * NN + KT2 + tid];
        nq = g_q[head * NN + KT2 + tid];
    }
    __syncthreads();

    for (int t = 0; t < NT2; t++) {
        const int buf = t & 1;
        const int nbuf = buf ^ 1;

        if (t + 1 < NT2) {
            if (stager) {
                unsigned char* ba = &Bsm[nbuf][0][sd * 64];
                unsigned char* bb = &Bsm[nbuf][1][sd * 64];
                *(uint32_t*)(ba + (((0 ^ skey) << 4) + ppos)) = nva.x;
                *(uint32_t*)(ba + (((1 ^ skey) << 4) + ppos)) = nva.y;
                *(uint32_t*)(ba + (((2 ^ skey) << 4) + ppos)) = nva.z;
                *(uint32_t*)(ba + (((3 ^ skey) << 4) + ppos)) = nva.w;
                *(uint32_t*)(bb + (((0 ^ skey) << 4) + ppos)) = nvb.x;
                *(uint32_t*)(bb + (((1 ^ skey) << 4) + ppos)) = nvb.y;
                *(uint32_t*)(bb + (((2 ^ skey) << 4) + ppos)) = nvb.z;
                *(uint32_t*)(bb + (((3 ^ skey) << 4) + ppos)) = nvb.w;
            }
            if (tid < KT2) QQ[nbuf][tid] = make_float2(nQ, nq);
        }

        // ---- A fragments: 2 m-frags, this warp's j-half ----
        uint32_t A[2][2][4];
#pragma unroll
        for (int mg = 0; mg < 2; mg++) {
            const unsigned ma = cm[2 * mg];
            const unsigned mb = cm[2 * mg + 1];
            const float Pa = Ps[2 * mg], pa = ps[2 * mg];
            const float Pb = Ps[2 * mg + 1], pb = ps[2 * mg + 1];
#pragma unroll
            for (int s = 0; s < 2; s++) {
                const int ja = 16 * s + 2 * c;
                const int jq = jh * 32 + ja;
                float2 qa0 = QQ[buf][jq];
                float2 qa1 = QQ[buf][jq + 1];
                float2 qb0 = QQ[buf][jq + 8];
                float2 qb1 = QQ[buf][jq + 9];
                float wa0 = fmaxf(Pa * qa0.x, pa * qa0.y); wa0 = ((ma >> ja)       & 1u) ? wa0 : 0.f;
                float wa1 = fmaxf(Pa * qa1.x, pa * qa1.y); wa1 = ((ma >> (ja + 1)) & 1u) ? wa1 : 0.f;
                float wa8 = fmaxf(Pa * qb0.x, pa * qb0.y); wa8 = ((ma >> (ja + 8)) & 1u) ? wa8 : 0.f;
                float wa9 = fmaxf(Pa * qb1.x, pa * qb1.y); wa9 = ((ma >> (ja + 9)) & 1u) ? wa9 : 0.f;
                float wb0 = fmaxf(Pb * qa0.x, pb * qa0.y); wb0 = ((mb >> ja)       & 1u) ? wb0 : 0.f;
                float wb1 = fmaxf(Pb * qa1.x, pb * qa1.y); wb1 = ((mb >> (ja + 1)) & 1u) ? wb1 : 0.f;
                float wb8 = fmaxf(Pb * qb0.x, pb * qb0.y); wb8 = ((mb >> (ja + 8)) & 1u) ? wb8 : 0.f;
                float wb9 = fmaxf(Pb * qb1.x, pb * qb1.y); wb9 = ((mb >> (ja + 9)) & 1u) ? wb9 : 0.f;
                A[mg][s][0] = packh2(wa1, wa0);
                A[mg][s][1] = packh2(wb1, wb0);
                A[mg][s][2] = packh2(wa9, wa8);
                A[mg][s][3] = packh2(wb9, wb8);
            }
        }

        // rotate masks, prefetch tile t+2
#pragma unroll
        for (int k = 0; k < 4; k++) cm[k] = nm[k];
        if (t + 2 < NT2) {
            const int j0 = (t + 2) * KT2;
            if (stager) {
                nva = *(const uint4*)(hp + j0 + q4 * 8);
                nvb = *(const uint4*)(hp + j0 + 32 + q4 * 8);
            }
#pragma unroll
            for (int k = 0; k < 4; k++) nm[k] = mp[k][2 * (t + 2) + jh];
            if (tid < KT2) {
                nQ = g_Q[head * NN + j0 + tid];
                nq = g_q[head * NN + j0 + tid];
            }
        }

        // ---- B loads (only this warp's j-half) + MMA ----
#pragma unroll
        for (int nt = 0; nt < 8; nt++) {
            const int d = nt * 8 + gr;
            const uint32_t off = (uint32_t)(d * 64 + ((c ^ (gr & 3)) << 4));
            uint4 v = *(const uint4*)(&Bsm[buf][jh][off]);
            mma_f16(acc[0][nt], A[0][0], v.x, v.y);
            mma_f16(acc[0][nt], A[0][1], v.z, v.w);
            mma_f16(acc[1][nt], A[1][0], v.x, v.y);
            mma_f16(acc[1][nt], A[1][1], v.z, v.w);
        }
        mma_f16(zacc[0], A[0][0], ONE2, ONE2);
        mma_f16(zacc[0], A[0][1], ONE2, ONE2);
        mma_f16(zacc[1], A[1][0], ONE2, ONE2);
        mma_f16(zacc[1], A[1][1], ONE2, ONE2);
        __syncthreads();
    }

    // ---- combine the two j-halves ----
#pragma unroll
    for (int mg = 0; mg < 2; mg++) {
        const int la = ir * 32 + mg * 16 + gr;
        zsh[jh][la]     = zacc[mg][0];
        zsh[jh][la + 8] = zacc[mg][2];
    }
    __syncthreads();
    const int cb = c * 2;
    if (jh == 1) {
#pragma unroll
        for (int mg = 0; mg < 2; mg++) {
            const int la = ir * 32 + mg * 16 + gr;
            const float iz0 = 1.0f / (zacc[mg][0] + zsh[0][la]);
            const float iz1 = 1.0f / (zacc[mg][2] + zsh[0][la + 8]);
            float* o0 = out + (size_t)(i0 + la) * OF + head * HD + cb;
            float* o1 = o0 + 8 * OF;
#pragma unroll
            for (int nt = 0; nt < 8; nt++) {
                *(float2*)(o0 + nt * 8) = make_float2(acc[mg][nt][0] * iz0, acc[mg][nt][1] * iz0);
                *(float2*)(o1 + nt * 8) = make_float2(acc[mg][nt][2] * iz1, acc[mg][nt][3] * iz1);
            }
        }
    }
    __syncthreads();
    if (jh == 0) {
#pragma unroll
        for (int mg = 0; mg < 2; mg++) {
            const int la = ir * 32 + mg * 16 + gr;
            const float iz0 = 1.0f / (zacc[mg][0] + zsh[1][la]);
            const float iz1 = 1.0f / (zacc[mg][2] + zsh[1][la + 8]);
            float* o0 = out + (size_t)(i0 + la) * OF + head * HD + cb;
            float* o1 = o0 + 8 * OF;
#pragma unroll
            for (int nt = 0; nt < 8; nt++) {
                float2 v0 = *(float2*)(o0 + nt * 8);
                float2 v1 = *(float2*)(o1 + nt * 8);
                v0.x += acc[mg][nt][0] * iz0; v0.y += acc[mg][nt][1] * iz0;
                v1.x += acc[mg][nt][2] * iz1; v1.y += acc[mg][nt][3] * iz1;
                *(float2*)(o0 + nt * 8) = v0;
                *(float2*)(o1 + nt * 8) = v1;
            }
        }
    }
}

// ---------------- launch ----------------
extern "C" void kernel_launch(void* const* d_in, const int* in_sizes, int n_in,
                              void* d_out, int out_size) {
    const float* x     = (const float*)d_in[0];
    const int*   adj   = (const int*)d_in[1];
    const float* W     = (const float*)d_in[2];
    const float* a_src = (const float*)d_in[3];
    const float* a_dst = (const float*)d_in[4];
    float* out = (float*)d_out;

    const int mask_blocks = (NN * (NN / 512) * 32) / 256;   // 2304
    prep_kernel<<<FSB + mask_blocks, 256>>>(x, W, adj);
    gemm_kernel<<<dim3(NN / 96, OF / 128), 384>>>();
    htrans_kernel<<<dim3(NN / 64, NH), 256>>>(a_src, a_dst);
    attn_kernel<<<dim3(NN / MT, NH), 384>>>(out);
}